// round 10
// baseline (speedup 1.0000x reference)
#include <cuda_runtime.h>
#include <cstdint>

// ---------------------------------------------------------------------------
// Compile-time G(3,0,1) blade algebra (verified: rel_err 8.5e-8).
// Basis order: 0:1 1:e0 2:e1 3:e2 4:e3 5:e01 6:e02 7:e03 8:e12 9:e13 10:e23
//              11:e012 12:e013 13:e023 14:e123 15:e0123
// ---------------------------------------------------------------------------

namespace ga {

__host__ __device__ constexpr int mask_of(int i) {
    const int t[16] = {0, 1, 2, 4, 8, 3, 5, 9, 6, 10, 12, 7, 11, 13, 14, 15};
    return t[i];
}
__host__ __device__ constexpr int idx_of(int m) {
    const int t[16] = {0, 1, 2, 5, 3, 6, 8, 11, 4, 7, 9, 12, 10, 13, 14, 15};
    return t[m];
}
__host__ __device__ constexpr int popc4(int m) {
    return (m & 1) + ((m >> 1) & 1) + ((m >> 2) & 1) + ((m >> 3) & 1);
}
__host__ __device__ constexpr int rsign(int a, int b) {
    int cnt = 0;
    for (int i = 1; i < 4; ++i)
        if ((a >> i) & 1) cnt += popc4(b & ((1 << i) - 1));
    return (cnt & 1) ? -1 : 1;
}

__host__ __device__ constexpr int gp_coef(int k, int j) {
    const int mk = mask_of(k), mj = mask_of(j);
    const int mi = mk ^ mj;
    if (mi & mj & 1) return 0;              // shared e0 -> metric 0
    return rsign(mi, mj);
}
__host__ __device__ constexpr int gp_src(int k, int j) {
    return idx_of(mask_of(k) ^ mask_of(j));
}

__host__ __device__ constexpr int jn_coef(int k, int j) {
    const int mk = mask_of(k), mj = mask_of(j);
    const int nmj = ~mj & 15;
    if (mk & nmj) return 0;                 // requires mk subset of mj
    const int mi = mk | nmj;
    return rsign(~mk & 15, mk)
         * rsign(mi, ~mi & 15)
         * rsign(mj, ~mj & 15)
         * rsign(~mi & 15, nmj);
}
__host__ __device__ constexpr int jn_src(int k, int j) {
    const int mk = mask_of(k), mj = mask_of(j);
    return idx_of(mk | (~mj & 15));
}

template <int K, int J>
__device__ __forceinline__ float gp_term(const float (&x)[16], const float (&y)[16]) {
    if constexpr (J >= 16) {
        return 0.0f;
    } else {
        float acc = gp_term<K, J + 1>(x, y);
        constexpr int c = gp_coef(K, J);
        constexpr int p = gp_src(K, J);
        if constexpr (c == 1)  acc = fmaf(x[p], y[J], acc);
        if constexpr (c == -1) acc = fmaf(-x[p], y[J], acc);
        return acc;
    }
}

template <int K, int J>
__device__ __forceinline__ float jn_term(const float (&x)[16], const float (&y)[16]) {
    if constexpr (J >= 16) {
        return 0.0f;
    } else {
        float acc = jn_term<K, J + 1>(x, y);
        constexpr int c = jn_coef(K, J);
        constexpr int p = jn_src(K, J);
        if constexpr (c == 1)  acc = fmaf(x[p], y[J], acc);
        if constexpr (c == -1) acc = fmaf(-x[p], y[J], acc);
        return acc;
    }
}

}  // namespace ga

// ---------------------------------------------------------------------------
// R9 transpose pipeline with two upgrades:
//   a) gmem->smem staging via cp.async.cg (LDGSTS): no transit registers,
//      all 8 copies per lane issue back-to-back fire-and-forget.
//   b) 6 CTAs/SM (42-reg budget) -- safe now because any rematerialization
//      under the tighter budget is an LDS from the staging buffer, not a
//      gmem reload (R6's failure mode is structurally impossible here).
// ---------------------------------------------------------------------------

constexpr int TPB = 256;
constexpr int WARPS_PER_CTA = TPB / 32;
constexpr int CH_STRIDE = 136;       // floats between chunk planes (544B)
constexpr int WBUF = 8 * CH_STRIDE;  // 1088 floats (>= 32*33 for output reuse)
constexpr int PITCH = 33;            // output transpose pitch (floats)

__device__ __forceinline__ void cp16(uint32_t dst, const void* src) {
    asm volatile("cp.async.cg.shared.global [%0], [%1], 16;\n" :: "r"(dst), "l"(src));
}
__device__ __forceinline__ void cp_commit_wait() {
    asm volatile("cp.async.commit_group;\n"
                 "cp.async.wait_group 0;\n" ::: "memory");
}

__global__ __launch_bounds__(TPB, 6)
void MVGeometricBilinear_kernel(const float4* __restrict__ x4,
                                const float4* __restrict__ y4,
                                const float* __restrict__ ref,
                                float* __restrict__ out,
                                int npts) {
    __shared__ __align__(16) float smem[WARPS_PER_CTA][WBUF];   // 34816 B

    const int tid  = threadIdx.x;
    const int lane = tid & 31;
    const int w    = tid >> 5;
    const int P0   = blockIdx.x * TPB + w * 32;      // warp's first point
    const int p    = P0 + lane;

    float* wbuf = smem[w];
    const uint32_t wb_s = (uint32_t)__cvta_generic_to_shared(wbuf);

    // ---- 1. coalesced gmem -> smem via cp.async (no transit registers) ----
    {
        const int nv  = npts - P0;
        const int nv4 = nv <= 0 ? 0 : (nv >= 32 ? 128 : nv * 4);
        const char* xw = (const char*)(x4 + (size_t)P0 * 4);
        const char* yw = (const char*)(y4 + (size_t)P0 * 4);
#pragma unroll
        for (int i = 0; i < 4; ++i) {
            const int g = i * 32 + lane;             // float4 index in block
            if (g < nv4) {
                const int c  = g & 3;                // chunk within point
                const int pp = g >> 2;               // local point
                cp16(wb_s + (uint32_t)(c * CH_STRIDE + pp * 4) * 4, xw + g * 16);
                cp16(wb_s + (uint32_t)((4 + c) * CH_STRIDE + pp * 4) * 4, yw + g * 16);
            }
        }
    }
    const float r15 = (p < npts) ? __ldcs(ref + (size_t)p * 16 + 15) : 0.0f;
    cp_commit_wait();
    __syncwarp();

    // ---- 2. smem -> regs (own point), conflict-free LDS.128 ----
    float x[16], y[16];
    if (p < npts) {
#pragma unroll
        for (int c = 0; c < 4; ++c) {
            const float4 vx = *(const float4*)(wbuf + c * CH_STRIDE + lane * 4);
            const float4 vy = *(const float4*)(wbuf + (4 + c) * CH_STRIDE + lane * 4);
            x[4*c+0]=vx.x; x[4*c+1]=vx.y; x[4*c+2]=vx.z; x[4*c+3]=vx.w;
            y[4*c+0]=vy.x; y[4*c+1]=vy.y; y[4*c+2]=vy.z; y[4*c+3]=vy.w;
        }
    }
    __syncwarp();   // all lanes done reading before buffer is overwritten

    // ---- 3. compute -> smem rows (pitch 33: bank = lane+k, conflict-free) ----
    if (p < npts) {
        float* row = wbuf + lane * PITCH;
#pragma unroll
        for (int k = 0; k < 16; ++k) {
            float v;
            switch (k) {
                case 0:  v = ga::gp_term<0, 0>(x, y);  break;
                case 1:  v = ga::gp_term<1, 0>(x, y);  break;
                case 2:  v = ga::gp_term<2, 0>(x, y);  break;
                case 3:  v = ga::gp_term<3, 0>(x, y);  break;
                case 4:  v = ga::gp_term<4, 0>(x, y);  break;
                case 5:  v = ga::gp_term<5, 0>(x, y);  break;
                case 6:  v = ga::gp_term<6, 0>(x, y);  break;
                case 7:  v = ga::gp_term<7, 0>(x, y);  break;
                case 8:  v = ga::gp_term<8, 0>(x, y);  break;
                case 9:  v = ga::gp_term<9, 0>(x, y);  break;
                case 10: v = ga::gp_term<10, 0>(x, y); break;
                case 11: v = ga::gp_term<11, 0>(x, y); break;
                case 12: v = ga::gp_term<12, 0>(x, y); break;
                case 13: v = ga::gp_term<13, 0>(x, y); break;
                case 14: v = ga::gp_term<14, 0>(x, y); break;
                default: v = ga::gp_term<15, 0>(x, y); break;
            }
            row[k] = v;
        }
#pragma unroll
        for (int k = 0; k < 16; ++k) {
            float v;
            switch (k) {
                case 0:  v = ga::jn_term<0, 0>(x, y);  break;
                case 1:  v = ga::jn_term<1, 0>(x, y);  break;
                case 2:  v = ga::jn_term<2, 0>(x, y);  break;
                case 3:  v = ga::jn_term<3, 0>(x, y);  break;
                case 4:  v = ga::jn_term<4, 0>(x, y);  break;
                case 5:  v = ga::jn_term<5, 0>(x, y);  break;
                case 6:  v = ga::jn_term<6, 0>(x, y);  break;
                case 7:  v = ga::jn_term<7, 0>(x, y);  break;
                case 8:  v = ga::jn_term<8, 0>(x, y);  break;
                case 9:  v = ga::jn_term<9, 0>(x, y);  break;
                case 10: v = ga::jn_term<10, 0>(x, y); break;
                case 11: v = ga::jn_term<11, 0>(x, y); break;
                case 12: v = ga::jn_term<12, 0>(x, y); break;
                case 13: v = ga::jn_term<13, 0>(x, y); break;
                case 14: v = ga::jn_term<14, 0>(x, y); break;
                default: v = ga::jn_term<15, 0>(x, y); break;
            }
            row[16 + k] = r15 * v;
        }
    }
    __syncwarp();

    // ---- 4. coalesced writeback: instruction i = point P0+i (one 128B line) ----
    const int nvalid = npts - P0;
    float* outw = out + (size_t)P0 * 32;
    if (nvalid >= 32) {
#pragma unroll
        for (int i = 0; i < 32; ++i)
            __stcs(outw + 32 * i + lane, wbuf[i * PITCH + lane]);
    } else if (nvalid > 0) {
        for (int i = 0; i < nvalid; ++i)
            __stcs(outw + 32 * i + lane, wbuf[i * PITCH + lane]);
    }
}

extern "C" void kernel_launch(void* const* d_in, const int* in_sizes, int n_in,
                              void* d_out, int out_size) {
    const float* x   = (const float*)d_in[0];
    const float* y   = (const float*)d_in[1];
    const float* ref = (const float*)d_in[2];
    float* out       = (float*)d_out;

    const int npts = in_sizes[0] / 16;
    const int blocks = (npts + TPB - 1) / TPB;

    MVGeometricBilinear_kernel<<<blocks, TPB>>>(
        (const float4*)x, (const float4*)y, ref, out, npts);
}

// round 11
// speedup vs baseline: 1.0495x; 1.0495x over previous
#include <cuda_runtime.h>
#include <cstdint>

// ---------------------------------------------------------------------------
// Compile-time G(3,0,1) blade algebra (verified: rel_err 8.5e-8).
// Basis order: 0:1 1:e0 2:e1 3:e2 4:e3 5:e01 6:e02 7:e03 8:e12 9:e13 10:e23
//              11:e012 12:e013 13:e023 14:e123 15:e0123
// ---------------------------------------------------------------------------

namespace ga {

__host__ __device__ constexpr int mask_of(int i) {
    const int t[16] = {0, 1, 2, 4, 8, 3, 5, 9, 6, 10, 12, 7, 11, 13, 14, 15};
    return t[i];
}
__host__ __device__ constexpr int idx_of(int m) {
    const int t[16] = {0, 1, 2, 5, 3, 6, 8, 11, 4, 7, 9, 12, 10, 13, 14, 15};
    return t[m];
}
__host__ __device__ constexpr int popc4(int m) {
    return (m & 1) + ((m >> 1) & 1) + ((m >> 2) & 1) + ((m >> 3) & 1);
}
__host__ __device__ constexpr int rsign(int a, int b) {
    int cnt = 0;
    for (int i = 1; i < 4; ++i)
        if ((a >> i) & 1) cnt += popc4(b & ((1 << i) - 1));
    return (cnt & 1) ? -1 : 1;
}

__host__ __device__ constexpr int gp_coef(int k, int j) {
    const int mk = mask_of(k), mj = mask_of(j);
    const int mi = mk ^ mj;
    if (mi & mj & 1) return 0;              // shared e0 -> metric 0
    return rsign(mi, mj);
}
__host__ __device__ constexpr int gp_src(int k, int j) {
    return idx_of(mask_of(k) ^ mask_of(j));
}

__host__ __device__ constexpr int jn_coef(int k, int j) {
    const int mk = mask_of(k), mj = mask_of(j);
    const int nmj = ~mj & 15;
    if (mk & nmj) return 0;                 // requires mk subset of mj
    const int mi = mk | nmj;
    return rsign(~mk & 15, mk)
         * rsign(mi, ~mi & 15)
         * rsign(mj, ~mj & 15)
         * rsign(~mi & 15, nmj);
}
__host__ __device__ constexpr int jn_src(int k, int j) {
    const int mk = mask_of(k), mj = mask_of(j);
    return idx_of(mk | (~mj & 15));
}

template <int K, int J>
__device__ __forceinline__ float gp_term(const float (&x)[16], const float (&y)[16]) {
    if constexpr (J >= 16) {
        return 0.0f;
    } else {
        float acc = gp_term<K, J + 1>(x, y);
        constexpr int c = gp_coef(K, J);
        constexpr int p = gp_src(K, J);
        if constexpr (c == 1)  acc = fmaf(x[p], y[J], acc);
        if constexpr (c == -1) acc = fmaf(-x[p], y[J], acc);
        return acc;
    }
}

template <int K, int J>
__device__ __forceinline__ float jn_term(const float (&x)[16], const float (&y)[16]) {
    if constexpr (J >= 16) {
        return 0.0f;
    } else {
        float acc = jn_term<K, J + 1>(x, y);
        constexpr int c = jn_coef(K, J);
        constexpr int p = jn_src(K, J);
        if constexpr (c == 1)  acc = fmaf(x[p], y[J], acc);
        if constexpr (c == -1) acc = fmaf(-x[p], y[J], acc);
        return acc;
    }
}

}  // namespace ga

// ---------------------------------------------------------------------------
// R9 pipeline (best: 24.96us kernel) with ONE change: gmem->smem staging via
// cp.async.cg (register-free, fire-and-forget) instead of LDG.128+STS.128,
// at the PROVEN 5 CTAs/SM (48-reg budget). R10 showed the 6-CTA reg squeeze
// destroys the compute phase; this isolates the staging upgrade.
// ---------------------------------------------------------------------------

constexpr int TPB = 256;
constexpr int WARPS_PER_CTA = TPB / 32;
constexpr int CH_STRIDE = 136;       // floats between chunk planes (544B)
constexpr int WBUF = 8 * CH_STRIDE;  // 1088 floats (>= 32*33 for output reuse)
constexpr int PITCH = 33;            // output transpose pitch (floats)

__device__ __forceinline__ void cp16(uint32_t dst, const void* src) {
    asm volatile("cp.async.cg.shared.global [%0], [%1], 16;\n" :: "r"(dst), "l"(src));
}
__device__ __forceinline__ void cp_commit_wait() {
    asm volatile("cp.async.commit_group;\n"
                 "cp.async.wait_group 0;\n" ::: "memory");
}

__global__ __launch_bounds__(TPB, 5)
void MVGeometricBilinear_kernel(const float4* __restrict__ x4,
                                const float4* __restrict__ y4,
                                const float* __restrict__ ref,
                                float* __restrict__ out,
                                int npts) {
    __shared__ __align__(16) float smem[WARPS_PER_CTA][WBUF];   // 34816 B

    const int tid  = threadIdx.x;
    const int lane = tid & 31;
    const int w    = tid >> 5;
    const int P0   = blockIdx.x * TPB + w * 32;      // warp's first point
    const int p    = P0 + lane;

    float* wbuf = smem[w];
    const uint32_t wb_s = (uint32_t)__cvta_generic_to_shared(wbuf);

    // ---- 1. coalesced gmem -> smem via cp.async (no transit registers) ----
    {
        const int nv  = npts - P0;
        const int nv4 = nv <= 0 ? 0 : (nv >= 32 ? 128 : nv * 4);
        const char* xw = (const char*)(x4 + (size_t)P0 * 4);
        const char* yw = (const char*)(y4 + (size_t)P0 * 4);
#pragma unroll
        for (int i = 0; i < 4; ++i) {
            const int g = i * 32 + lane;             // float4 index in block
            if (g < nv4) {
                const int c  = g & 3;                // chunk within point
                const int pp = g >> 2;               // local point
                cp16(wb_s + (uint32_t)(c * CH_STRIDE + pp * 4) * 4, xw + g * 16);
                cp16(wb_s + (uint32_t)((4 + c) * CH_STRIDE + pp * 4) * 4, yw + g * 16);
            }
        }
    }
    const float r15 = (p < npts) ? __ldcs(ref + (size_t)p * 16 + 15) : 0.0f;
    cp_commit_wait();
    __syncwarp();

    // ---- 2. smem -> regs (own point), conflict-free LDS.128 ----
    float x[16], y[16];
    if (p < npts) {
#pragma unroll
        for (int c = 0; c < 4; ++c) {
            const float4 vx = *(const float4*)(wbuf + c * CH_STRIDE + lane * 4);
            const float4 vy = *(const float4*)(wbuf + (4 + c) * CH_STRIDE + lane * 4);
            x[4*c+0]=vx.x; x[4*c+1]=vx.y; x[4*c+2]=vx.z; x[4*c+3]=vx.w;
            y[4*c+0]=vy.x; y[4*c+1]=vy.y; y[4*c+2]=vy.z; y[4*c+3]=vy.w;
        }
    }
    __syncwarp();   // all lanes done reading before buffer is overwritten

    // ---- 3. compute -> smem rows (pitch 33: bank = lane+k, conflict-free) ----
    if (p < npts) {
        float* row = wbuf + lane * PITCH;
#pragma unroll
        for (int k = 0; k < 16; ++k) {
            float v;
            switch (k) {
                case 0:  v = ga::gp_term<0, 0>(x, y);  break;
                case 1:  v = ga::gp_term<1, 0>(x, y);  break;
                case 2:  v = ga::gp_term<2, 0>(x, y);  break;
                case 3:  v = ga::gp_term<3, 0>(x, y);  break;
                case 4:  v = ga::gp_term<4, 0>(x, y);  break;
                case 5:  v = ga::gp_term<5, 0>(x, y);  break;
                case 6:  v = ga::gp_term<6, 0>(x, y);  break;
                case 7:  v = ga::gp_term<7, 0>(x, y);  break;
                case 8:  v = ga::gp_term<8, 0>(x, y);  break;
                case 9:  v = ga::gp_term<9, 0>(x, y);  break;
                case 10: v = ga::gp_term<10, 0>(x, y); break;
                case 11: v = ga::gp_term<11, 0>(x, y); break;
                case 12: v = ga::gp_term<12, 0>(x, y); break;
                case 13: v = ga::gp_term<13, 0>(x, y); break;
                case 14: v = ga::gp_term<14, 0>(x, y); break;
                default: v = ga::gp_term<15, 0>(x, y); break;
            }
            row[k] = v;
        }
#pragma unroll
        for (int k = 0; k < 16; ++k) {
            float v;
            switch (k) {
                case 0:  v = ga::jn_term<0, 0>(x, y);  break;
                case 1:  v = ga::jn_term<1, 0>(x, y);  break;
                case 2:  v = ga::jn_term<2, 0>(x, y);  break;
                case 3:  v = ga::jn_term<3, 0>(x, y);  break;
                case 4:  v = ga::jn_term<4, 0>(x, y);  break;
                case 5:  v = ga::jn_term<5, 0>(x, y);  break;
                case 6:  v = ga::jn_term<6, 0>(x, y);  break;
                case 7:  v = ga::jn_term<7, 0>(x, y);  break;
                case 8:  v = ga::jn_term<8, 0>(x, y);  break;
                case 9:  v = ga::jn_term<9, 0>(x, y);  break;
                case 10: v = ga::jn_term<10, 0>(x, y); break;
                case 11: v = ga::jn_term<11, 0>(x, y); break;
                case 12: v = ga::jn_term<12, 0>(x, y); break;
                case 13: v = ga::jn_term<13, 0>(x, y); break;
                case 14: v = ga::jn_term<14, 0>(x, y); break;
                default: v = ga::jn_term<15, 0>(x, y); break;
            }
            row[16 + k] = r15 * v;
        }
    }
    __syncwarp();

    // ---- 4. coalesced writeback: instruction i = point P0+i (one 128B line) ----
    const int nvalid = npts - P0;
    float* outw = out + (size_t)P0 * 32;
    if (nvalid >= 32) {
#pragma unroll
        for (int i = 0; i < 32; ++i)
            __stcs(outw + 32 * i + lane, wbuf[i * PITCH + lane]);
    } else if (nvalid > 0) {
        for (int i = 0; i < nvalid; ++i)
            __stcs(outw + 32 * i + lane, wbuf[i * PITCH + lane]);
    }
}

extern "C" void kernel_launch(void* const* d_in, const int* in_sizes, int n_in,
                              void* d_out, int out_size) {
    const float* x   = (const float*)d_in[0];
    const float* y   = (const float*)d_in[1];
    const float* ref = (const float*)d_in[2];
    float* out       = (float*)d_out;

    const int npts = in_sizes[0] / 16;
    const int blocks = (npts + TPB - 1) / TPB;

    MVGeometricBilinear_kernel<<<blocks, TPB>>>(
        (const float4*)x, (const float4*)y, ref, out, npts);
}

// round 12
// speedup vs baseline: 1.2810x; 1.2206x over previous
#include <cuda_runtime.h>

// ---------------------------------------------------------------------------
// Compile-time G(3,0,1) blade algebra (verified: rel_err 8.5e-8).
// Basis order: 0:1 1:e0 2:e1 3:e2 4:e3 5:e01 6:e02 7:e03 8:e12 9:e13 10:e23
//              11:e012 12:e013 13:e023 14:e123 15:e0123
// ---------------------------------------------------------------------------

namespace ga {

__host__ __device__ constexpr int mask_of(int i) {
    const int t[16] = {0, 1, 2, 4, 8, 3, 5, 9, 6, 10, 12, 7, 11, 13, 14, 15};
    return t[i];
}
__host__ __device__ constexpr int idx_of(int m) {
    const int t[16] = {0, 1, 2, 5, 3, 6, 8, 11, 4, 7, 9, 12, 10, 13, 14, 15};
    return t[m];
}
__host__ __device__ constexpr int popc4(int m) {
    return (m & 1) + ((m >> 1) & 1) + ((m >> 2) & 1) + ((m >> 3) & 1);
}
__host__ __device__ constexpr int rsign(int a, int b) {
    int cnt = 0;
    for (int i = 1; i < 4; ++i)
        if ((a >> i) & 1) cnt += popc4(b & ((1 << i) - 1));
    return (cnt & 1) ? -1 : 1;
}

__host__ __device__ constexpr int gp_coef(int k, int j) {
    const int mk = mask_of(k), mj = mask_of(j);
    const int mi = mk ^ mj;
    if (mi & mj & 1) return 0;              // shared e0 -> metric 0
    return rsign(mi, mj);
}
__host__ __device__ constexpr int gp_src(int k, int j) {
    return idx_of(mask_of(k) ^ mask_of(j));
}

__host__ __device__ constexpr int jn_coef(int k, int j) {
    const int mk = mask_of(k), mj = mask_of(j);
    const int nmj = ~mj & 15;
    if (mk & nmj) return 0;                 // requires mk subset of mj
    const int mi = mk | nmj;
    return rsign(~mk & 15, mk)
         * rsign(mi, ~mi & 15)
         * rsign(mj, ~mj & 15)
         * rsign(~mi & 15, nmj);
}
__host__ __device__ constexpr int jn_src(int k, int j) {
    const int mk = mask_of(k), mj = mask_of(j);
    return idx_of(mk | (~mj & 15));
}

template <int K, int J>
__device__ __forceinline__ float gp_term(const float (&x)[16], const float (&y)[16]) {
    if constexpr (J >= 16) {
        return 0.0f;
    } else {
        float acc = gp_term<K, J + 1>(x, y);
        constexpr int c = gp_coef(K, J);
        constexpr int p = gp_src(K, J);
        if constexpr (c == 1)  acc = fmaf(x[p], y[J], acc);
        if constexpr (c == -1) acc = fmaf(-x[p], y[J], acc);
        return acc;
    }
}

template <int K, int J>
__device__ __forceinline__ float jn_term(const float (&x)[16], const float (&y)[16]) {
    if constexpr (J >= 16) {
        return 0.0f;
    } else {
        float acc = jn_term<K, J + 1>(x, y);
        constexpr int c = jn_coef(K, J);
        constexpr int p = jn_src(K, J);
        if constexpr (c == 1)  acc = fmaf(x[p], y[J], acc);
        if constexpr (c == -1) acc = fmaf(-x[p], y[J], acc);
        return acc;
    }
}

template <int K>
__device__ __forceinline__ float4 gp_quad(const float (&x)[16], const float (&y)[16]) {
    return make_float4(gp_term<K + 0, 0>(x, y), gp_term<K + 1, 0>(x, y),
                       gp_term<K + 2, 0>(x, y), gp_term<K + 3, 0>(x, y));
}

template <int K>
__device__ __forceinline__ float4 jn_quad(const float (&x)[16], const float (&y)[16],
                                          float r15) {
    return make_float4(r15 * jn_term<K + 0, 0>(x, y), r15 * jn_term<K + 1, 0>(x, y),
                       r15 * jn_term<K + 2, 0>(x, y), r15 * jn_term<K + 3, 0>(x, y));
}

}  // namespace ga

// ---------------------------------------------------------------------------
// R9 pipeline (proven best: 24.96us) with the smem output transpose fully
// vectorized: PITCH 33 -> 36 floats (16B-aligned rows) so the per-thread
// output writes are 8 STS.128 and the writeback is 8 LDS.128 + 8 STG.128
// per warp (was 32+32+32 scalar ops). Same wavefront counts, 72 fewer
// instructions per warp. Staging identical to R9 (cp.async falsified
// R10/R11; LDG->STS wins).
// ---------------------------------------------------------------------------

constexpr int TPB = 256;
constexpr int WARPS_PER_CTA = TPB / 32;
constexpr int CH_STRIDE = 136;       // floats between staging chunk planes
constexpr int PITCH = 36;            // output row pitch: 144B, 16B-aligned
constexpr int WBUF = 32 * PITCH;     // 1152 floats (also >= 8*CH_STRIDE=1088)

__global__ __launch_bounds__(TPB, 5)
void MVGeometricBilinear_kernel(const float4* __restrict__ x4,
                                const float4* __restrict__ y4,
                                const float* __restrict__ ref,
                                float* __restrict__ out,
                                int npts) {
    __shared__ __align__(16) float smem[WARPS_PER_CTA][WBUF];   // 36864 B

    const int tid  = threadIdx.x;
    const int lane = tid & 31;
    const int w    = tid >> 5;
    const int P0   = blockIdx.x * TPB + w * 32;      // warp's first point
    const int p    = P0 + lane;

    float* wbuf = smem[w];

    // ---- 1. coalesced gmem -> smem (R9 staging: LDG.128 + STS.128) ----
    {
        const int nv  = npts - P0;
        const int nv4 = nv <= 0 ? 0 : (nv >= 32 ? 128 : nv * 4);
        const float4* xw = x4 + (size_t)P0 * 4;
        const float4* yw = y4 + (size_t)P0 * 4;
#pragma unroll
        for (int i = 0; i < 4; ++i) {
            const int g = i * 32 + lane;             // float4 index in block
            if (g < nv4) {
                const int c  = g & 3;                // chunk within point
                const int pp = g >> 2;               // local point
                *(float4*)(wbuf + c * CH_STRIDE + pp * 4)       = __ldcs(xw + g);
                *(float4*)(wbuf + (4 + c) * CH_STRIDE + pp * 4) = __ldcs(yw + g);
            }
        }
    }
    const float r15 = (p < npts) ? __ldcs(ref + (size_t)p * 16 + 15) : 0.0f;
    __syncwarp();

    // ---- 2. smem -> regs (own point), conflict-free LDS.128 ----
    float x[16], y[16];
    if (p < npts) {
#pragma unroll
        for (int c = 0; c < 4; ++c) {
            const float4 vx = *(const float4*)(wbuf + c * CH_STRIDE + lane * 4);
            const float4 vy = *(const float4*)(wbuf + (4 + c) * CH_STRIDE + lane * 4);
            x[4*c+0]=vx.x; x[4*c+1]=vx.y; x[4*c+2]=vx.z; x[4*c+3]=vx.w;
            y[4*c+0]=vy.x; y[4*c+1]=vy.y; y[4*c+2]=vy.z; y[4*c+3]=vy.w;
        }
    }
    __syncwarp();   // all lanes done reading before buffer is overwritten

    // ---- 3. compute -> smem rows via STS.128 (pitch 36: conflict-free) ----
    if (p < npts) {
        float4* row4 = (float4*)(wbuf + lane * PITCH);
        row4[0] = ga::gp_quad<0>(x, y);
        row4[1] = ga::gp_quad<4>(x, y);
        row4[2] = ga::gp_quad<8>(x, y);
        row4[3] = ga::gp_quad<12>(x, y);
        row4[4] = ga::jn_quad<0>(x, y, r15);
        row4[5] = ga::jn_quad<4>(x, y, r15);
        row4[6] = ga::jn_quad<8>(x, y, r15);
        row4[7] = ga::jn_quad<12>(x, y, r15);
    }
    __syncwarp();

    // ---- 4. vectorized coalesced writeback: 8x (LDS.128 + STG.128) ----
    // instr i, lane L covers warp-block floats 128i+4L..+3
    //   = row (4i + L/8), comps 4(L%8)..+3; smem banks 4(L%8): conflict-free.
    const int nvalid = npts - P0;
    float* outw = out + (size_t)P0 * 32;
    if (nvalid >= 32) {
#pragma unroll
        for (int i = 0; i < 8; ++i) {
            const int r = 4 * i + (lane >> 3);
            const int c = 4 * (lane & 7);
            const float4 v = *(const float4*)(wbuf + r * PITCH + c);
            __stcs((float4*)(outw + 128 * i + 4 * lane), v);
        }
    } else if (nvalid > 0) {
        for (int i = 0; i < nvalid; ++i)
            __stcs(outw + 32 * i + lane, wbuf[i * PITCH + lane]);
    }
}

extern "C" void kernel_launch(void* const* d_in, const int* in_sizes, int n_in,
                              void* d_out, int out_size) {
    const float* x   = (const float*)d_in[0];
    const float* y   = (const float*)d_in[1];
    const float* ref = (const float*)d_in[2];
    float* out       = (float*)d_out;

    const int npts = in_sizes[0] / 16;
    const int blocks = (npts + TPB - 1) / TPB;

    MVGeometricBilinear_kernel<<<blocks, TPB>>>(
        (const float4*)x, (const float4*)y, ref, out, npts);
}